// round 17
// baseline (speedup 1.0000x reference)
#include <cuda_runtime.h>

#define N_CLASS   10
#define PSTRIDE   12
#define MAX_NODES 100000

typedef unsigned long long ull;

__device__ __align__(16) float g_P[MAX_NODES * PSTRIDE];
__device__ __align__(16) float g_Q[MAX_NODES * PSTRIDE];

#define FFMA2(acc, a, b) \
    asm("fma.rn.f32x2 %0, %1, %2, %0;" : "+l"(acc) : "l"(a), "l"(b))
#define FMUL2(r, a, b) \
    asm("mul.rn.f32x2 %0, %1, %2;" : "=l"(r) : "l"(a), "l"(b))
#define FADD2(r, a, b) \
    asm("add.rn.f32x2 %0, %1, %2;" : "=l"(r) : "l"(a), "l"(b))

__device__ __forceinline__ ull pack2(float x, float y) {
    ull r;
    asm("mov.b64 %0, {%1, %2};" : "=l"(r) : "f"(x), "f"(y));
    return r;
}
__device__ __forceinline__ float2 unpack2(ull p) {
    float2 f;
    asm("mov.b64 {%0, %1}, %2;" : "=f"(f.x), "=f"(f.y) : "l"(p));
    return f;
}

// lane-resident weights: wp[p][k] = (W[2p][col], W[2p+1][col]) for this lane's 4 cols
__device__ __forceinline__ void load_weights(const float* __restrict__ W, int wcol,
                                             int lane, ull wp[5][4]) {
#pragma unroll
    for (int p = 0; p < 5; p++) {
        float4 wa = ((const float4*)(W + (2 * p) * 384 + wcol))[lane];
        float4 wb = ((const float4*)(W + (2 * p + 1) * 384 + wcol))[lane];
        wp[p][0] = pack2(wa.x, wb.x);
        wp[p][1] = pack2(wa.y, wb.y);
        wp[p][2] = pack2(wa.z, wb.z);
        wp[p][3] = pack2(wa.w, wb.w);
    }
}

// First step uses MUL (no zero-init), rest FMA.
__device__ __forceinline__ void dot10f(const ull wp[5][4], float4 v, ull acc[5]) {
    ull a0 = pack2(v.x, v.x);
    ull a1 = pack2(v.y, v.y);
    ull a2 = pack2(v.z, v.z);
    ull a3 = pack2(v.w, v.w);
#pragma unroll
    for (int p = 0; p < 5; p++) {
        FMUL2(acc[p], a0, wp[p][0]);
        FFMA2(acc[p], a1, wp[p][1]);
        FFMA2(acc[p], a2, wp[p][2]);
        FFMA2(acc[p], a3, wp[p][3]);
    }
}

// Hybrid reduction (R15 proven): slot-ordered SEL-free folds on unpacked
// 32-bit floats (10 independent shallow chains). Slots A=ent k, B=k^1,
// C=k^2, D=k^3, k = ((o&1)<<1)|(o>>1). Every lane of octet o ends with the
// full 10-class result of entity k(o).
__device__ __forceinline__ void reduce_hyb(const ull aA[5], const ull aB[5],
                                           const ull aC[5], const ull aD[5],
                                           float u[N_CLASS]) {
    float pA[N_CLASS], pB[N_CLASS], pC[N_CLASS], pD[N_CLASS];
#pragma unroll
    for (int q = 0; q < 5; q++) {
        float2 f;
        f = unpack2(aA[q]); pA[2 * q] = f.x; pA[2 * q + 1] = f.y;
        f = unpack2(aB[q]); pB[2 * q] = f.x; pB[2 * q + 1] = f.y;
        f = unpack2(aC[q]); pC[2 * q] = f.x; pC[2 * q + 1] = f.y;
        f = unpack2(aD[q]); pD[2 * q] = f.x; pD[2 * q + 1] = f.y;
    }
#pragma unroll
    for (int c = 0; c < N_CLASS; c++) {
        float t  = pA[c] + __shfl_xor_sync(0xffffffffu, pB[c], 16);
        float t2 = pC[c] + __shfl_xor_sync(0xffffffffu, pD[c], 16);
        float w  = t + __shfl_xor_sync(0xffffffffu, t2, 8);
        w += __shfl_xor_sync(0xffffffffu, w, 4);
        w += __shfl_xor_sync(0xffffffffu, w, 2);
        w += __shfl_xor_sync(0xffffffffu, w, 1);
        u[c] = w;
    }
}

// ---------------------------------------------------------------------------
// Fused single-read node projection. Entities per pass (2 rows):
//   e = (proj<<1)|row : row = e&1, proj = e>>1 (0 -> g_P/W1+b, 1 -> g_Q/W2).
// Each lane holds BOTH weight slices (wpA for slots A,B; wpB for C,D);
// slot/fold algebra identical to R15 (xor16 flips row, xor8 flips proj).
// h is read ONCE (51MB vs 102MB before).
// ---------------------------------------------------------------------------
__global__ __launch_bounds__(128)
void proj_kernel(const float* __restrict__ X, const float* __restrict__ W,
                 const float* __restrict__ bias, int n_rows) {
    int lane = threadIdx.x & 31;
    int warp = (blockIdx.x * blockDim.x + threadIdx.x) >> 5;
    int nwarps = (gridDim.x * blockDim.x) >> 5;
    int o = lane >> 3, j = lane & 7;
    int k = ((o & 1) << 1) | (o >> 1);
    int rsel = k & 1;          // row for slots A, C
    int wsel = k >> 1;         // weight set for slots A, B
    int stride = nwarps * 2;

    ull wpA[5][4], wpB[5][4];
    load_weights(W, wsel ? 128 : 0, lane, wpA);
    load_weights(W, wsel ? 0 : 128, lane, wpB);

    // packed per-lane bias slice for this lane's store role (j<3),
    // applied only when this octet's entity is a P entity (wsel==0).
    ull bp0 = 0ull, bp1 = 0ull;
    if (wsel == 0 && j < 3) {
        if (j < 2) {
            bp0 = pack2(__ldg(bias + 4 * j), __ldg(bias + 4 * j + 1));
            bp1 = pack2(__ldg(bias + 4 * j + 2), __ldg(bias + 4 * j + 3));
        } else {
            bp0 = pack2(__ldg(bias + 8), __ldg(bias + 9));
        }
    }

    const float4* Xv = (const float4*)X;
    int nm1 = n_rows - 1;
    int base = warp * 2;
    if (base >= n_rows) return;

    float4 v0 = Xv[(size_t)min(base + rsel, nm1) * 32 + lane];        // slot A,C row
    float4 v1 = Xv[(size_t)min(base + (rsel ^ 1), nm1) * 32 + lane];  // slot B,D row

    while (true) {
        int nb = base + stride;
        bool has_next = nb < n_rows;
        float4 n0, n1;
        if (has_next) {
            n0 = Xv[(size_t)min(nb + rsel, nm1) * 32 + lane];
            n1 = Xv[(size_t)min(nb + (rsel ^ 1), nm1) * 32 + lane];
        }

        ull aA[5], aB[5], aC[5], aD[5];
        dot10f(wpA, v0, aA);
        dot10f(wpA, v1, aB);
        dot10f(wpB, v0, aC);
        dot10f(wpB, v1, aD);

        float u[N_CLASS];
        reduce_hyb(aA, aB, aC, aD, u);

        // entity k: row base+rsel, projection wsel
        int ridx = base + rsel;
        if (ridx < n_rows && j < 3) {
            float* outbuf = wsel ? g_Q : g_P;
            ull* O = (ull*)(outbuf + (size_t)ridx * PSTRIDE);
            if (j == 0) {
                ull r0, r1;
                FADD2(r0, pack2(u[0], u[1]), bp0);
                FADD2(r1, pack2(u[2], u[3]), bp1);
                O[0] = r0; O[1] = r1;
            } else if (j == 1) {
                ull r0, r1;
                FADD2(r0, pack2(u[4], u[5]), bp0);
                FADD2(r1, pack2(u[6], u[7]), bp1);
                O[2] = r0; O[3] = r1;
            } else {
                ull r0;
                FADD2(r0, pack2(u[8], u[9]), bp0);
                O[4] = r0;
            }
        }

        if (!has_next) break;
        base = nb;
        v0 = n0; v1 = n1;
    }
}

// ---------------------------------------------------------------------------
// Edge kernel: EXACT R15 body + occupancy cap (128 threads, min 5 blocks/SM).
// out[e] = eh[e] @ W[:,256:384]^T + P[src[e]] + Q[dst[e]]
// ---------------------------------------------------------------------------
__global__ __launch_bounds__(128, 5)
void edge_score_kernel(const float* __restrict__ eh, const float* __restrict__ W,
                       const int* __restrict__ src, const int* __restrict__ dst,
                       float* __restrict__ out, int n_edges) {
    int lane = threadIdx.x & 31;
    int warp = (blockIdx.x * blockDim.x + threadIdx.x) >> 5;
    int nwarps = (gridDim.x * blockDim.x) >> 5;
    int o = lane >> 3, j = lane & 7;
    int k = ((o & 1) << 1) | (o >> 1);
    int kB = k ^ 1, kC = k ^ 2, kD = k ^ 3;
    int stride = nwarps * 4;

    ull wp[5][4];
    load_weights(W, 256, lane, wp);

    const float4* Ev = (const float4*)eh;
    int nm1 = n_edges - 1;
    int base = warp * 4;
    if (base >= n_edges) return;

    float4 vA = Ev[(size_t)min(base + k, nm1) * 32 + lane];
    float4 vB = Ev[(size_t)min(base + kB, nm1) * 32 + lane];
    float4 vC = Ev[(size_t)min(base + kC, nm1) * 32 + lane];
    float4 vD = Ev[(size_t)min(base + kD, nm1) * 32 + lane];
    int ce = min(base + k, nm1);
    int s = src[ce], d = dst[ce];               // broadcast within octet

    while (true) {
        int nb = base + stride;
        bool has_next = nb < n_edges;
        float4 nA, nB, nC, nD;
        int ns = 0, nd = 0;
        if (has_next) {
            nA = Ev[(size_t)min(nb + k, nm1) * 32 + lane];
            nB = Ev[(size_t)min(nb + kB, nm1) * 32 + lane];
            nC = Ev[(size_t)min(nb + kC, nm1) * 32 + lane];
            nD = Ev[(size_t)min(nb + kD, nm1) * 32 + lane];
            int ne = min(nb + k, nm1);
            ns = src[ne]; nd = dst[ne];
        }

        ull aA[5], aB[5], aC[5], aD[5];
        dot10f(wp, vA, aA);
        dot10f(wp, vB, aB);
        dot10f(wp, vC, aC);
        dot10f(wp, vD, aD);

        float u[N_CLASS];
        reduce_hyb(aA, aB, aC, aD, u);

        int eidx = base + k;
        if (eidx < n_edges && j < 3) {
            float4 p = ((const float4*)(g_P + (size_t)s * PSTRIDE))[j];
            float4 q = ((const float4*)(g_Q + (size_t)d * PSTRIDE))[j];
            float2* o2 = (float2*)(out + (size_t)eidx * N_CLASS);
            if (j == 0) {
                o2[0] = make_float2(u[0] + p.x + q.x, u[1] + p.y + q.y);
                o2[1] = make_float2(u[2] + p.z + q.z, u[3] + p.w + q.w);
            } else if (j == 1) {
                o2[2] = make_float2(u[4] + p.x + q.x, u[5] + p.y + q.y);
                o2[3] = make_float2(u[6] + p.z + q.z, u[7] + p.w + q.w);
            } else {
                o2[4] = make_float2(u[8] + p.x + q.x, u[9] + p.y + q.y);
            }
        }

        if (!has_next) break;
        base = nb;
        vA = nA; vB = nB; vC = nC; vD = nD;
        s = ns; d = nd;
    }
}

// ---------------------------------------------------------------------------
extern "C" void kernel_launch(void* const* d_in, const int* in_sizes, int n_in,
                              void* d_out, int out_size) {
    const float* h   = (const float*)d_in[0];
    const float* eh  = (const float*)d_in[1];
    const float* W   = (const float*)d_in[2];
    const float* b   = (const float*)d_in[3];
    const int*   src = (const int*)d_in[4];
    const int*   dst = (const int*)d_in[5];
    float*       out = (float*)d_out;

    int n_nodes = in_sizes[0] / 128;
    int n_edges = in_sizes[4];

    proj_kernel<<<1184, 128>>>(h, W, b, n_nodes);          // fused P+Q, h read once
    edge_score_kernel<<<1184, 128>>>(eh, W, src, dst, out, n_edges);
}